// round 15
// baseline (speedup 1.0000x reference)
#include <cuda_runtime.h>
#include <cstddef>

// ---------------------------------------------------------------------------
// KGAT forward: 3 x (COO SpMM -> bi-interaction (2 small GEMMs) -> LeakyReLU
//               -> sum -> L2 normalize) + concat into (N, 176) output.
//
// N = 170000, NNZ = 2.72M, dims 64 -> 64 -> 32 -> 16.
// Scratch: __device__ globals (no allocation anywhere).
// ---------------------------------------------------------------------------

#define NMAX 170000

__device__ float g_side[(size_t)NMAX * 64];
__device__ float g_egoA[(size_t)NMAX * 64];
__device__ float g_egoB[(size_t)NMAX * 64];

// ---------------------------------------------------------------------------
// Vector reduction: red.global.add.v4.f32 (sm_90+)
// ---------------------------------------------------------------------------
__device__ __forceinline__ void red_add_v4(float* addr, float4 v) {
    asm volatile("red.global.add.v4.f32 [%0], {%1, %2, %3, %4};"
                 :: "l"(addr), "f"(v.x), "f"(v.y), "f"(v.z), "f"(v.w)
                 : "memory");
}

// ---------------------------------------------------------------------------
// Zero-fill (float4 granularity)
// ---------------------------------------------------------------------------
__global__ void zero4_kernel(float4* __restrict__ p, int n4) {
    int i = blockIdx.x * blockDim.x + threadIdx.x;
    if (i < n4) p[i] = make_float4(0.f, 0.f, 0.f, 0.f);
}

// ---------------------------------------------------------------------------
// Copy raw embeddings into output columns [0, 64)
// out row stride = 176 floats; col offset 0 is 16B-aligned (176 % 4 == 0).
// ---------------------------------------------------------------------------
__global__ void copy_emb_kernel(const float4* __restrict__ emb,
                                float* __restrict__ out, int n) {
    int i = blockIdx.x * blockDim.x + threadIdx.x;   // over n*16 float4 chunks
    if (i >= n * 16) return;
    int node = i >> 4;
    int c    = i & 15;
    float4 v = emb[(size_t)node * 16 + c];
    *reinterpret_cast<float4*>(&out[(size_t)node * 176 + c * 4]) = v;
}

// ---------------------------------------------------------------------------
// SpMM scatter: side[rows[e]] += vals[e] * ego[cols[e]]
// One thread per (edge, 4-column chunk). Consecutive threads share an edge
// -> edge metadata loads broadcast in L1, ego gathers coalesce per edge row.
// ---------------------------------------------------------------------------
template <int DIN>
__global__ void spmm_scatter_kernel(const float* __restrict__ vals,
                                    const int*   __restrict__ rows,
                                    const int*   __restrict__ cols,
                                    const float* __restrict__ ego,
                                    float*       __restrict__ side,
                                    int nnz) {
    constexpr unsigned C = DIN / 4;      // float4 chunks per row (16 or 8)
    unsigned t = blockIdx.x * blockDim.x + threadIdx.x;
    unsigned e = t / C;
    unsigned c = t % C;
    if (e >= (unsigned)nnz) return;

    int   r  = __ldg(&rows[e]);
    int   cl = __ldg(&cols[e]);
    float v  = __ldg(&vals[e]);

    float4 x = *reinterpret_cast<const float4*>(ego + (size_t)cl * DIN + c * 4);
    float4 m = make_float4(x.x * v, x.y * v, x.z * v, x.w * v);
    red_add_v4(side + (size_t)r * DIN + c * 4, m);
}

// ---------------------------------------------------------------------------
// Fused bi-interaction transform + LeakyReLU + sum + L2-norm + output write.
//   sum_e = leaky((e + s) @ W1 + b1)
//   bi_e  = leaky((e * s) @ W2 + b2)
//   ego'  = sum_e + bi_e          (written to ego_out, stride DOUT)
//   out[:, OFF:OFF+DOUT] = l2norm(ego')
// One warp per node; weights + per-node (e+s)/(e*s) staged in SMEM.
// Each lane owns outputs o = lane + 32*j  (j < ceil(DOUT/32)).
// ---------------------------------------------------------------------------
template <int DIN, int DOUT, int OFF>
__global__ void __launch_bounds__(256)
transform_kernel(const float* __restrict__ ego,
                 const float* __restrict__ side,
                 const float* __restrict__ w1, const float* __restrict__ b1,
                 const float* __restrict__ w2, const float* __restrict__ b2,
                 float* __restrict__ ego_out,
                 float* __restrict__ out, int n) {
    __shared__ float sW1[DIN * DOUT];
    __shared__ float sW2[DIN * DOUT];
    __shared__ float sb1[DOUT];
    __shared__ float sb2[DOUT];
    __shared__ float sSum[8][DIN];
    __shared__ float sPrd[8][DIN];

    int tid = threadIdx.x;
    for (int i = tid; i < DIN * DOUT; i += 256) {
        sW1[i] = w1[i];
        sW2[i] = w2[i];
    }
    for (int i = tid; i < DOUT; i += 256) {
        sb1[i] = b1[i];
        sb2[i] = b2[i];
    }
    __syncthreads();

    int warp = tid >> 5;
    int lane = tid & 31;
    int node = blockIdx.x * 8 + warp;
    if (node >= n) return;

    const float* ep = ego  + (size_t)node * DIN;
    const float* sp = side + (size_t)node * DIN;
    #pragma unroll
    for (int k = lane; k < DIN; k += 32) {
        float e = ep[k];
        float s = sp[k];
        sSum[warp][k] = e + s;
        sPrd[warp][k] = e * s;
    }
    __syncwarp();

    constexpr int J = (DOUT + 31) / 32;
    float a1[J], a2[J];
    #pragma unroll
    for (int j = 0; j < J; j++) {
        int o = lane + 32 * j;
        a1[j] = (o < DOUT) ? sb1[o] : 0.f;
        a2[j] = (o < DOUT) ? sb2[o] : 0.f;
    }

    #pragma unroll 4
    for (int k = 0; k < DIN; k++) {
        float su = sSum[warp][k];   // LDS broadcast (conflict-free)
        float pr = sPrd[warp][k];
        #pragma unroll
        for (int j = 0; j < J; j++) {
            int o = lane + 32 * j;
            if (o < DOUT) {
                a1[j] = fmaf(su, sW1[k * DOUT + o], a1[j]);
                a2[j] = fmaf(pr, sW2[k * DOUT + o], a2[j]);
            }
        }
    }

    float v[J];
    float ss = 0.f;
    #pragma unroll
    for (int j = 0; j < J; j++) {
        int o = lane + 32 * j;
        if (o < DOUT) {
            float x1 = a1[j]; x1 = (x1 >= 0.f) ? x1 : 0.01f * x1;  // LeakyReLU
            float x2 = a2[j]; x2 = (x2 >= 0.f) ? x2 : 0.01f * x2;
            v[j] = x1 + x2;
            ss   = fmaf(v[j], v[j], ss);
        } else {
            v[j] = 0.f;
        }
    }
    #pragma unroll
    for (int d = 16; d > 0; d >>= 1)
        ss += __shfl_xor_sync(0xffffffffu, ss, d);

    float sc = 1.0f / fmaxf(sqrtf(ss), 1e-12f);

    #pragma unroll
    for (int j = 0; j < J; j++) {
        int o = lane + 32 * j;
        if (o < DOUT) {
            ego_out[(size_t)node * DOUT + o]   = v[j];
            out[(size_t)node * 176 + OFF + o]  = v[j] * sc;
        }
    }
}

// ---------------------------------------------------------------------------
// Launch
// ---------------------------------------------------------------------------
extern "C" void kernel_launch(void* const* d_in, const int* in_sizes, int n_in,
                              void* d_out, int out_size) {
    const float* emb    = (const float*)d_in[0];
    const float* a_vals = (const float*)d_in[1];
    const float* w1_0 = (const float*)d_in[2];
    const float* b1_0 = (const float*)d_in[3];
    const float* w2_0 = (const float*)d_in[4];
    const float* b2_0 = (const float*)d_in[5];
    const float* w1_1 = (const float*)d_in[6];
    const float* b1_1 = (const float*)d_in[7];
    const float* w2_1 = (const float*)d_in[8];
    const float* b2_1 = (const float*)d_in[9];
    const float* w1_2 = (const float*)d_in[10];
    const float* b1_2 = (const float*)d_in[11];
    const float* w2_2 = (const float*)d_in[12];
    const float* b2_2 = (const float*)d_in[13];
    const int* a_rows = (const int*)d_in[14];
    const int* a_cols = (const int*)d_in[15];

    const int nnz = in_sizes[1];
    const int n   = in_sizes[0] / 64;
    float* out = (float*)d_out;

    float *side = nullptr, *egoA = nullptr, *egoB = nullptr;
    cudaGetSymbolAddress((void**)&side, g_side);
    cudaGetSymbolAddress((void**)&egoA, g_egoA);
    cudaGetSymbolAddress((void**)&egoB, g_egoB);

    const int TB = 256;

    // out[:, 0:64] = embeddings (raw, not normalized)
    copy_emb_kernel<<<(n * 16 + TB - 1) / TB, TB>>>((const float4*)emb, out, n);

    // ---- layer 0: 64 -> 64, output cols [64, 128) ----
    zero4_kernel<<<(n * 16 + TB - 1) / TB, TB>>>((float4*)side, n * 16);
    {
        long long threads = (long long)nnz * 16;
        spmm_scatter_kernel<64><<<(unsigned)((threads + TB - 1) / TB), TB>>>(
            a_vals, a_rows, a_cols, emb, side, nnz);
    }
    transform_kernel<64, 64, 64><<<(n + 7) / 8, TB>>>(
        emb, side, w1_0, b1_0, w2_0, b2_0, egoA, out, n);

    // ---- layer 1: 64 -> 32, output cols [128, 160) ----
    zero4_kernel<<<(n * 16 + TB - 1) / TB, TB>>>((float4*)side, n * 16);
    {
        long long threads = (long long)nnz * 16;
        spmm_scatter_kernel<64><<<(unsigned)((threads + TB - 1) / TB), TB>>>(
            a_vals, a_rows, a_cols, egoA, side, nnz);
    }
    transform_kernel<64, 32, 128><<<(n + 7) / 8, TB>>>(
        egoA, side, w1_1, b1_1, w2_1, b2_1, egoB, out, n);

    // ---- layer 2: 32 -> 16, output cols [160, 176) ----
    zero4_kernel<<<(n * 8 + TB - 1) / TB, TB>>>((float4*)side, n * 8);
    {
        long long threads = (long long)nnz * 8;
        spmm_scatter_kernel<32><<<(unsigned)((threads + TB - 1) / TB), TB>>>(
            a_vals, a_rows, a_cols, egoB, side, nnz);
    }
    transform_kernel<32, 16, 160><<<(n + 7) / 8, TB>>>(
        egoB, side, w1_2, b1_2, w2_2, b2_2, egoA, out, n);
}

// round 16
// speedup vs baseline: 1.1586x; 1.1586x over previous
#include <cuda_runtime.h>
#include <cstddef>
#include <cstdint>

// ---------------------------------------------------------------------------
// KGAT forward, round 15.
//   - COO -> CSR built on device each call (deterministic work, no allocs).
//   - SpMM: warp-per-row gather + register accumulate (no float atomics).
//   - Transform: register-tiled dual-GEMM (8 nodes x 4 outs x {W1,W2} per
//     thread), weights + (e+s)/(e*s) tiles in dynamic SMEM, fused LeakyReLU,
//     bi-interaction sum, L2-norm, strided concat write.
// ---------------------------------------------------------------------------

#define NMAX   170000
#define NNZMAX 2720000

__device__ float g_side[(size_t)NMAX * 64];
__device__ float g_egoA[(size_t)NMAX * 64];
__device__ float g_egoB[(size_t)NMAX * 64];
__device__ int   g_rowptr[NMAX + 1];
__device__ int   g_cnt[NMAX];          // counts, then exclusive-scan cursor
__device__ int2  g_edges[NNZMAX];      // (col, val-bits) grouped by row

// ---------------------------------------------------------------------------
// CSR build
// ---------------------------------------------------------------------------
__global__ void zeroi_kernel(int* __restrict__ p, int n) {
    int i = blockIdx.x * blockDim.x + threadIdx.x;
    if (i < n) p[i] = 0;
}

__global__ void hist_kernel(const int* __restrict__ rows, int* __restrict__ cnt,
                            int nnz) {
    int e = blockIdx.x * blockDim.x + threadIdx.x;
    if (e < nnz) atomicAdd(&cnt[rows[e]], 1);
}

// Single-block exclusive scan: cnt[i] (counts) -> rowptr[i] and cnt[i] (cursor).
__global__ void __launch_bounds__(1024) scan_kernel(int* __restrict__ cnt,
                                                    int* __restrict__ rowptr,
                                                    int n) {
    __shared__ int sdata[1024];
    __shared__ int s_run;
    int tid = threadIdx.x;
    if (tid == 0) s_run = 0;
    __syncthreads();

    for (int base = 0; base < n; base += 1024) {
        int i = base + tid;
        int x = (i < n) ? cnt[i] : 0;
        sdata[tid] = x;
        __syncthreads();
        #pragma unroll
        for (int off = 1; off < 1024; off <<= 1) {
            int y = (tid >= off) ? sdata[tid - off] : 0;
            __syncthreads();
            sdata[tid] += y;
            __syncthreads();
        }
        int excl = sdata[tid] - x + s_run;
        if (i < n) {
            rowptr[i] = excl;
            cnt[i]    = excl;     // cursor for permute pass
        }
        int tot = sdata[1023];
        __syncthreads();
        if (tid == 0) s_run += tot;
        __syncthreads();
    }
    if (tid == 0) rowptr[n] = s_run;
}

__global__ void permute_kernel(const int* __restrict__ rows,
                               const int* __restrict__ cols,
                               const float* __restrict__ vals,
                               int* __restrict__ cursor,
                               int2* __restrict__ edges, int nnz) {
    int e = blockIdx.x * blockDim.x + threadIdx.x;
    if (e >= nnz) return;
    int r = rows[e];
    int slot = atomicAdd(&cursor[r], 1);
    edges[slot] = make_int2(cols[e], __float_as_int(vals[e]));
}

// ---------------------------------------------------------------------------
// CSR SpMM: one warp per destination row, register accumulation, no atomics.
// Also serves as the zero-fill (rows with no edges write zeros).
// ---------------------------------------------------------------------------
template <int DIN>
__global__ void __launch_bounds__(256)
spmm_csr_kernel(const int* __restrict__ rowptr, const int2* __restrict__ edges,
                const float* __restrict__ ego, float* __restrict__ side, int n) {
    int warp = (int)((blockIdx.x * blockDim.x + threadIdx.x) >> 5);
    int lane = threadIdx.x & 31;
    if (warp >= n) return;

    int beg = __ldg(&rowptr[warp]);
    int end = __ldg(&rowptr[warp + 1]);

    if constexpr (DIN == 64) {
        float ax = 0.f, ay = 0.f;
        int e = beg;
        for (; e + 2 <= end; e += 2) {
            int2 d0 = __ldg(&edges[e]);
            int2 d1 = __ldg(&edges[e + 1]);
            float2 x0 = __ldg((const float2*)(ego + (size_t)d0.x * 64) + lane);
            float2 x1 = __ldg((const float2*)(ego + (size_t)d1.x * 64) + lane);
            float v0 = __int_as_float(d0.y);
            float v1 = __int_as_float(d1.y);
            ax = fmaf(v0, x0.x, ax); ay = fmaf(v0, x0.y, ay);
            ax = fmaf(v1, x1.x, ax); ay = fmaf(v1, x1.y, ay);
        }
        if (e < end) {
            int2 d0 = __ldg(&edges[e]);
            float2 x0 = __ldg((const float2*)(ego + (size_t)d0.x * 64) + lane);
            float v0 = __int_as_float(d0.y);
            ax = fmaf(v0, x0.x, ax); ay = fmaf(v0, x0.y, ay);
        }
        float2 r; r.x = ax; r.y = ay;
        ((float2*)(side + (size_t)warp * 64))[lane] = r;
    } else {  // DIN == 32
        float a = 0.f;
        int e = beg;
        for (; e + 2 <= end; e += 2) {
            int2 d0 = __ldg(&edges[e]);
            int2 d1 = __ldg(&edges[e + 1]);
            float x0 = __ldg(ego + (size_t)d0.x * 32 + lane);
            float x1 = __ldg(ego + (size_t)d1.x * 32 + lane);
            a = fmaf(__int_as_float(d0.y), x0, a);
            a = fmaf(__int_as_float(d1.y), x1, a);
        }
        if (e < end) {
            int2 d0 = __ldg(&edges[e]);
            float x0 = __ldg(ego + (size_t)d0.x * 32 + lane);
            a = fmaf(__int_as_float(d0.y), x0, a);
        }
        side[(size_t)warp * 32 + lane] = a;
    }
}

// ---------------------------------------------------------------------------
// Copy raw embeddings into output columns [0, 64)
// ---------------------------------------------------------------------------
__global__ void copy_emb_kernel(const float4* __restrict__ emb,
                                float* __restrict__ out, int n) {
    int i = blockIdx.x * blockDim.x + threadIdx.x;
    if (i >= n * 16) return;
    int node = i >> 4;
    int c    = i & 15;
    float4 v = emb[(size_t)node * 16 + c];
    *reinterpret_cast<float4*>(&out[(size_t)node * 176 + c * 4]) = v;
}

// ---------------------------------------------------------------------------
// Register-tiled bi-interaction transform.
//   Block tile: NT nodes x DOUT outputs. Thread micro-tile: 8 nodes x 4 outs,
//   BOTH matrices (64 accumulators). 128 threads = (NT/8) x (DOUT/4).
//   sum_e = leaky((e+s)@W1+b1); bi_e = leaky((e*s)@W2+b2); v = sum_e+bi_e
//   ego_out = v; out[:,OFF:OFF+DOUT] = v / max(||v||, 1e-12)
// ---------------------------------------------------------------------------
union F4 { float4 v; float f[4]; };

template <int DIN, int DOUT, int OFF, int NT>
__global__ void __launch_bounds__(128)
transform_kernel(const float* __restrict__ ego,
                 const float* __restrict__ side,
                 const float* __restrict__ w1, const float* __restrict__ b1,
                 const float* __restrict__ w2, const float* __restrict__ b2,
                 float* __restrict__ ego_out,
                 float* __restrict__ out, int n) {
    constexpr int DINP = DIN + 4;          // padded row (16B-aligned rows)
    constexpr int OT   = DOUT / 4;         // out tiles
    // threads = (NT/8) * OT == 128

    extern __shared__ float sm[];
    float* sSum  = sm;                         // NT * DINP
    float* sPrd  = sSum + NT * DINP;           // NT * DINP
    float* sW1   = sPrd + NT * DINP;           // DIN * DOUT
    float* sW2   = sW1  + DIN * DOUT;          // DIN * DOUT
    float* sNorm = sW2  + DIN * DOUT;          // NT

    int tid   = threadIdx.x;
    int node0 = blockIdx.x * NT;

    // Stage weights (k-major, contiguous outputs)
    for (int i = tid; i < DIN * DOUT; i += 128) {
        sW1[i] = __ldg(&w1[i]);
        sW2[i] = __ldg(&w2[i]);
    }
    // Stage A tiles: sum = e+s, prd = e*s  (node-major, padded rows)
    for (int idx = tid; idx < NT * (DIN / 4); idx += 128) {
        int nd = idx / (DIN / 4);
        int kk = idx % (DIN / 4);
        float4 e = make_float4(0.f, 0.f, 0.f, 0.f);
        float4 s = e;
        if (node0 + nd < n) {
            e = *reinterpret_cast<const float4*>(ego  + (size_t)(node0 + nd) * DIN + kk * 4);
            s = *reinterpret_cast<const float4*>(side + (size_t)(node0 + nd) * DIN + kk * 4);
        }
        float4 su = make_float4(e.x + s.x, e.y + s.y, e.z + s.z, e.w + s.w);
        float4 pr = make_float4(e.x * s.x, e.y * s.y, e.z * s.z, e.w * s.w);
        *reinterpret_cast<float4*>(&sSum[nd * DINP + kk * 4]) = su;
        *reinterpret_cast<float4*>(&sPrd[nd * DINP + kk * 4]) = pr;
    }
    for (int i = tid; i < NT; i += 128) sNorm[i] = 0.f;
    __syncthreads();

    int ot  = tid % OT;            // output tile
    int ntl = tid / OT;            // node tile (8 nodes)

    float b1a[4], b2a[4];
    #pragma unroll
    for (int j = 0; j < 4; j++) {
        b1a[j] = __ldg(&b1[ot * 4 + j]);
        b2a[j] = __ldg(&b2[ot * 4 + j]);
    }

    float acc1[8][4], acc2[8][4];
    #pragma unroll
    for (int i = 0; i < 8; i++)
        #pragma unroll
        for (int j = 0; j < 4; j++) { acc1[i][j] = b1a[j]; acc2[i][j] = b2a[j]; }

    // Mainloop over k in chunks of 4
    for (int k4 = 0; k4 < DIN; k4 += 4) {
        F4 w1f[4], w2f[4];
        #pragma unroll
        for (int kk = 0; kk < 4; kk++) {
            w1f[kk].v = *reinterpret_cast<const float4*>(&sW1[(k4 + kk) * DOUT + ot * 4]);
            w2f[kk].v = *reinterpret_cast<const float4*>(&sW2[(k4 + kk) * DOUT + ot * 4]);
        }
        #pragma unroll
        for (int i = 0; i < 8; i++) {
            F4 su, pr;
            su.v = *reinterpret_cast<const float4*>(&sSum[(ntl * 8 + i) * DINP + k4]);
            pr.v = *reinterpret_cast<const float4*>(&sPrd[(ntl * 8 + i) * DINP + k4]);
            #pragma unroll
            for (int kk = 0; kk < 4; kk++) {
                float sv = su.f[kk], pv = pr.f[kk];
                #pragma unroll
                for (int j = 0; j < 4; j++) {
                    acc1[i][j] = fmaf(sv, w1f[kk].f[j], acc1[i][j]);
                    acc2[i][j] = fmaf(pv, w2f[kk].f[j], acc2[i][j]);
                }
            }
        }
    }

    // Epilogue: leaky + sum, per-node sumsq into shared; v overwrites acc1.
    #pragma unroll
    for (int i = 0; i < 8; i++) {
        float ss = 0.f;
        #pragma unroll
        for (int j = 0; j < 4; j++) {
            float x1 = acc1[i][j]; x1 = (x1 >= 0.f) ? x1 : 0.01f * x1;
            float x2 = acc2[i][j]; x2 = (x2 >= 0.f) ? x2 : 0.01f * x2;
            float v = x1 + x2;
            acc1[i][j] = v;
            ss = fmaf(v, v, ss);
        }
        atomicAdd(&sNorm[ntl * 8 + i], ss);
    }
    __syncthreads();

    #pragma unroll
    for (int i = 0; i < 8; i++) {
        int nd   = ntl * 8 + i;
        int node = node0 + nd;
        if (node >= n) continue;
        float sc = 1.0f / fmaxf(sqrtf(sNorm[nd]), 1e-12f);
        float4 ve = make_float4(acc1[i][0], acc1[i][1], acc1[i][2], acc1[i][3]);
        float4 vo = make_float4(ve.x * sc, ve.y * sc, ve.z * sc, ve.w * sc);
        *reinterpret_cast<float4*>(&ego_out[(size_t)node * DOUT + ot * 4]) = ve;
        *reinterpret_cast<float4*>(&out[(size_t)node * 176 + OFF + ot * 4]) = vo;
    }
}

// ---------------------------------------------------------------------------
// Launch
// ---------------------------------------------------------------------------
extern "C" void kernel_launch(void* const* d_in, const int* in_sizes, int n_in,
                              void* d_out, int out_size) {
    const float* emb    = (const float*)d_in[0];
    const float* a_vals = (const float*)d_in[1];
    const float* w1_0 = (const float*)d_in[2];
    const float* b1_0 = (const float*)d_in[3];
    const float* w2_0 = (const float*)d_in[4];
    const float* b2_0 = (const float*)d_in[5];
    const float* w1_1 = (const float*)d_in[6];
    const float* b1_1 = (const float*)d_in[7];
    const float* w2_1 = (const float*)d_in[8];
    const float* b2_1 = (const float*)d_in[9];
    const float* w1_2 = (const float*)d_in[10];
    const float* b1_2 = (const float*)d_in[11];
    const float* w2_2 = (const float*)d_in[12];
    const float* b2_2 = (const float*)d_in[13];
    const int* a_rows = (const int*)d_in[14];
    const int* a_cols = (const int*)d_in[15];

    const int nnz = in_sizes[1];
    const int n   = in_sizes[0] / 64;
    float* out = (float*)d_out;

    float *side = nullptr, *egoA = nullptr, *egoB = nullptr;
    int *rowptr = nullptr, *cnt = nullptr;
    int2 *edges = nullptr;
    cudaGetSymbolAddress((void**)&side,   g_side);
    cudaGetSymbolAddress((void**)&egoA,   g_egoA);
    cudaGetSymbolAddress((void**)&egoB,   g_egoB);
    cudaGetSymbolAddress((void**)&rowptr, g_rowptr);
    cudaGetSymbolAddress((void**)&cnt,    g_cnt);
    cudaGetSymbolAddress((void**)&edges,  g_edges);

    const int TB = 256;

    // Dynamic SMEM opt-in for the transform instantiations (attributes are
    // process-persistent; first call sets them before graph capture).
    constexpr int SM0 = (2 * 64  * 68 + 2 * 64 * 64 + 64)  * 4;  // 67,840 B
    constexpr int SM1 = (2 * 128 * 68 + 2 * 64 * 32 + 128) * 4;  // 86,528 B
    constexpr int SM2 = (2 * 256 * 36 + 2 * 32 * 16 + 256) * 4;  // 78,848 B
    cudaFuncSetAttribute((const void*)transform_kernel<64, 64, 64, 64>,
                         cudaFuncAttributeMaxDynamicSharedMemorySize, SM0);
    cudaFuncSetAttribute((const void*)transform_kernel<64, 32, 128, 128>,
                         cudaFuncAttributeMaxDynamicSharedMemorySize, SM1);
    cudaFuncSetAttribute((const void*)transform_kernel<32, 16, 160, 256>,
                         cudaFuncAttributeMaxDynamicSharedMemorySize, SM2);

    // out[:, 0:64] = raw embeddings
    copy_emb_kernel<<<(n * 16 + TB - 1) / TB, TB>>>((const float4*)emb, out, n);

    // ---- CSR build (every call; deterministic work) ----
    zeroi_kernel<<<(n + TB - 1) / TB, TB>>>(cnt, n);
    hist_kernel<<<(nnz + TB - 1) / TB, TB>>>(a_rows, cnt, nnz);
    scan_kernel<<<1, 1024>>>(cnt, rowptr, n);
    permute_kernel<<<(nnz + TB - 1) / TB, TB>>>(a_rows, a_cols, a_vals, cnt,
                                                edges, nnz);

    const int spmm_blocks = (n + 7) / 8;   // 8 warps/block, warp-per-row

    // ---- layer 0: 64 -> 64, cols [64,128) ----
    spmm_csr_kernel<64><<<spmm_blocks, TB>>>(rowptr, edges, emb, side, n);
    transform_kernel<64, 64, 64, 64><<<(n + 63) / 64, 128, SM0>>>(
        emb, side, w1_0, b1_0, w2_0, b2_0, egoA, out, n);

    // ---- layer 1: 64 -> 32, cols [128,160) ----
    spmm_csr_kernel<64><<<spmm_blocks, TB>>>(rowptr, edges, egoA, side, n);
    transform_kernel<64, 32, 128, 128><<<(n + 127) / 128, 128, SM1>>>(
        egoA, side, w1_1, b1_1, w2_1, b2_1, egoB, out, n);

    // ---- layer 2: 32 -> 16, cols [160,176) ----
    spmm_csr_kernel<32><<<spmm_blocks, TB>>>(rowptr, edges, egoB, side, n);
    transform_kernel<32, 16, 160, 256><<<(n + 255) / 256, 128, SM2>>>(
        egoB, side, w1_2, b1_2, w2_2, b2_2, egoA, out, n);
}